// round 10
// baseline (speedup 1.0000x reference)
#include <cuda_runtime.h>
#include <cuda_bf16.h>
#include <math_constants.h>

// RoI max pooling (Caffe-style), bit-matching the JAX/XLA:CPU reference.
// VERIFIED ARITHMETIC (R6, rel_err==0.0) — do not alter:
//   rs*    = rintf(__fmul_rn(coord, scale))
//   bh/bw  = __fmul_rn(roi_extent, 1.0f/7.0f)   (XLA fast-math reciprocal form)
//   hstart = floorf(__fmul_rn(ph, bh)) + rsh ; hend = ceilf(__fmul_rn(ph+1,bh)) + rsh
//   clip to [0,64]; empty bin (hend<=hstart || wend<=wstart) -> 0.
//
// Two kernels:
//  1) transpose [B,C,H*W] -> [B,H*W,C] scratch (channel-fastest).
//  2) pool: block = (roi, ph), 256 threads = 256 channels. All loop bounds
//     are UNIFORM across the block (same roi) -> zero divergence; loads are
//     dt[(b,h,w), c] -> 128B-coalesced per warp. This removes both R6
//     pathologies (scattered loads + warp-max trip counts) at once.

#define CROP_H 7
#define CROP_W 7
#define NROI   128
#define HH     64
#define WW     64
#define HW     (HH * WW)
#define CC     256
#define BB     4

__device__ float g_dt[BB * HW * CC];   // 16 MB transposed data

// ---------------- transpose: [b][c][hw] -> [b][hw][c] ----------------
__global__ __launch_bounds__(256)
void transpose_kernel(const float* __restrict__ in)
{
    __shared__ float tile[32][33];
    int b   = blockIdx.z;
    int hw0 = blockIdx.x * 32;
    int c0  = blockIdx.y * 32;

    const float* src = in   + (size_t)b * CC * HW;
    float*       dst = g_dt + (size_t)b * HW * CC;

    #pragma unroll
    for (int i = threadIdx.y; i < 32; i += 8)
        tile[i][threadIdx.x] = src[(size_t)(c0 + i) * HW + hw0 + threadIdx.x];
    __syncthreads();
    #pragma unroll
    for (int i = threadIdx.y; i < 32; i += 8)
        dst[(size_t)(hw0 + i) * CC + c0 + threadIdx.x] = tile[threadIdx.x][i];
}

// ---------------- pool: block = (n, ph), thread = channel ----------------
__global__ __launch_bounds__(256)
void pool_kernel(const float* __restrict__ rois,
                 const int*   __restrict__ roibatches,
                 const float* __restrict__ scale_ptr,
                 float* __restrict__ out)
{
    int n  = blockIdx.x / CROP_H;
    int ph = blockIdx.x - n * CROP_H;
    int c  = threadIdx.x;

    // ---- geometry (uniform across block; verified arithmetic) ----
    float scale = __ldg(scale_ptr);
    float x1 = __ldg(&rois[n * 4 + 0]);
    float y1 = __ldg(&rois[n * 4 + 1]);
    float x2 = __ldg(&rois[n * 4 + 2]);
    float y2 = __ldg(&rois[n * 4 + 3]);

    int rsw = (int)rintf(__fmul_rn(x1, scale));
    int rsh = (int)rintf(__fmul_rn(y1, scale));
    int rew = (int)rintf(__fmul_rn(x2, scale));
    int reh = (int)rintf(__fmul_rn(y2, scale));

    float roi_h = (float)max(reh - rsh + 1, 1);
    float roi_w = (float)max(rew - rsw + 1, 1);
    const float RCP7 = 1.0f / 7.0f;
    float bh = __fmul_rn(roi_h, RCP7);
    float bw = __fmul_rn(roi_w, RCP7);

    int hs = (int)floorf(__fmul_rn((float)ph, bh)) + rsh;
    int he = (int)ceilf (__fmul_rn((float)ph + 1.0f, bh)) + rsh;
    hs = min(max(hs, 0), HH);
    he = min(max(he, 0), HH);

    int b = __ldg(&roibatches[n]);
    const float* base = g_dt + ((size_t)b * HW) * CC + c;

    float* out_nc = out + (size_t)n * (CC * CROP_H * CROP_W)
                        + (size_t)c * (CROP_H * CROP_W) + ph * CROP_W;

    #pragma unroll
    for (int pw = 0; pw < CROP_W; ++pw) {
        int ws = (int)floorf(__fmul_rn((float)pw, bw)) + rsw;
        int we = (int)ceilf (__fmul_rn((float)pw + 1.0f, bw)) + rsw;
        ws = min(max(ws, 0), WW);
        we = min(max(we, 0), WW);

        float m;
        if (he <= hs || we <= ws) {
            m = 0.0f;
        } else {
            m = -CUDART_INF_F;
            for (int h = hs; h < he; ++h) {
                const float* p = base + (size_t)(h * WW + ws) * CC;
                for (int w = ws; w < we; ++w) {
                    m = fmaxf(m, __ldg(p));
                    p += CC;
                }
            }
        }
        out_nc[pw] = m;
    }
}

extern "C" void kernel_launch(void* const* d_in, const int* in_sizes, int n_in,
                              void* d_out, int out_size)
{
    const float* data      = nullptr;
    const float* rois      = nullptr;
    const int*   batches   = nullptr;
    const float* scale_ptr = nullptr;

    for (int i = 0; i < n_in; ++i) {
        int sz = in_sizes[i];
        if (sz == 1)            scale_ptr = (const float*)d_in[i];
        else if (sz == 128)     batches   = (const int*)d_in[i];
        else if (sz == 512)     rois      = (const float*)d_in[i];
        else                    data      = (const float*)d_in[i];
    }

    float* out = (float*)d_out;

    dim3 tgrid(HW / 32, CC / 32, BB);     // 128 x 8 x 4 = 4096 blocks
    dim3 tblock(32, 8);
    transpose_kernel<<<tgrid, tblock>>>(data);

    pool_kernel<<<NROI * CROP_H, 256>>>(rois, batches, scale_ptr, out);
}

// round 11
// speedup vs baseline: 1.8521x; 1.8521x over previous
#include <cuda_runtime.h>
#include <cuda_bf16.h>
#include <math_constants.h>

// RoI max pooling (Caffe-style), bit-matching the JAX/XLA:CPU reference.
// VERIFIED ARITHMETIC (R6, rel_err==0.0) — do not alter:
//   rs*    = rintf(__fmul_rn(coord, scale))
//   bh/bw  = __fmul_rn(roi_extent, 1.0f/7.0f)   (XLA fast-math reciprocal form)
//   hstart = floorf(__fmul_rn(ph, bh)) + rsh ; hend = ceilf(__fmul_rn(ph+1,bh)) + rsh
//   clip to [0,64]; empty bin (hend<=hstart || wend<=wstart) -> 0.
//
// Kernel 1: transpose [B,C,H*W] -> [B,H*W,C] (channel-fastest scratch).
// Kernel 2: pool. Block = (n, ph, pw) = 6272 blocks x 64 threads; thread
// owns 4 consecutive channels (one float4 per window element). Bounds are
// block-uniform (no divergence), loads coalesced 16B/lane, ~12 independent
// loads/thread (high MLP), 400k threads (hides L2 latency that starved R10).

#define CROP_H 7
#define CROP_W 7
#define NROI   128
#define HH     64
#define WW     64
#define HW     (HH * WW)
#define CC     256
#define BB     4

__device__ float g_dt[BB * HW * CC];   // 16 MB transposed data

// ---------------- transpose: [b][c][hw] -> [b][hw][c] ----------------
__global__ __launch_bounds__(256)
void transpose_kernel(const float* __restrict__ in)
{
    __shared__ float tile[32][33];
    int b   = blockIdx.z;
    int hw0 = blockIdx.x * 32;
    int c0  = blockIdx.y * 32;

    const float* src = in   + (size_t)b * CC * HW;
    float*       dst = g_dt + (size_t)b * HW * CC;

    #pragma unroll
    for (int i = threadIdx.y; i < 32; i += 8)
        tile[i][threadIdx.x] = src[(size_t)(c0 + i) * HW + hw0 + threadIdx.x];
    __syncthreads();
    #pragma unroll
    for (int i = threadIdx.y; i < 32; i += 8)
        dst[(size_t)(hw0 + i) * CC + c0 + threadIdx.x] = tile[threadIdx.x][i];
}

// ---------------- pool: block = (n, ph, pw), thread = 4 channels ----------------
__global__ __launch_bounds__(64)
void pool_kernel(const float* __restrict__ rois,
                 const int*   __restrict__ roibatches,
                 const float* __restrict__ scale_ptr,
                 float* __restrict__ out)
{
    int bi = blockIdx.x;
    int pw = bi % CROP_W;
    int t  = bi / CROP_W;
    int ph = t % CROP_H;
    int n  = t / CROP_H;

    // ---- geometry (uniform across block; verified arithmetic) ----
    float scale = __ldg(scale_ptr);
    float x1 = __ldg(&rois[n * 4 + 0]);
    float y1 = __ldg(&rois[n * 4 + 1]);
    float x2 = __ldg(&rois[n * 4 + 2]);
    float y2 = __ldg(&rois[n * 4 + 3]);

    int rsw = (int)rintf(__fmul_rn(x1, scale));
    int rsh = (int)rintf(__fmul_rn(y1, scale));
    int rew = (int)rintf(__fmul_rn(x2, scale));
    int reh = (int)rintf(__fmul_rn(y2, scale));

    float roi_h = (float)max(reh - rsh + 1, 1);
    float roi_w = (float)max(rew - rsw + 1, 1);
    const float RCP7 = 1.0f / 7.0f;
    float bh = __fmul_rn(roi_h, RCP7);
    float bw = __fmul_rn(roi_w, RCP7);

    int hs = (int)floorf(__fmul_rn((float)ph, bh)) + rsh;
    int he = (int)ceilf (__fmul_rn((float)ph + 1.0f, bh)) + rsh;
    int ws = (int)floorf(__fmul_rn((float)pw, bw)) + rsw;
    int we = (int)ceilf (__fmul_rn((float)pw + 1.0f, bw)) + rsw;
    hs = min(max(hs, 0), HH);
    he = min(max(he, 0), HH);
    ws = min(max(ws, 0), WW);
    we = min(max(we, 0), WW);

    int b = __ldg(&roibatches[n]);
    // float4 view: CC/4 = 64 float4 per pixel; lane tid owns channels 4*tid..
    const float4* base = (const float4*)(g_dt + (size_t)b * HW * CC);
    int tid = threadIdx.x;

    float4 m;
    if (he <= hs || we <= ws) {
        m = make_float4(0.0f, 0.0f, 0.0f, 0.0f);
    } else {
        m = make_float4(-CUDART_INF_F, -CUDART_INF_F, -CUDART_INF_F, -CUDART_INF_F);
        for (int h = hs; h < he; ++h) {
            const float4* rowp = base + (size_t)(h * WW + ws) * (CC / 4) + tid;
            for (int w = ws; w < we; ++w) {
                float4 v = __ldg(rowp);
                m.x = fmaxf(m.x, v.x);
                m.y = fmaxf(m.y, v.y);
                m.z = fmaxf(m.z, v.z);
                m.w = fmaxf(m.w, v.w);
                rowp += CC / 4;
            }
        }
    }

    int c0 = tid * 4;
    size_t ob = (((size_t)n * CC + c0) * CROP_H + ph) * CROP_W + pw;
    const size_t cs = CROP_H * CROP_W;   // stride between channels
    out[ob]          = m.x;
    out[ob + cs]     = m.y;
    out[ob + 2 * cs] = m.z;
    out[ob + 3 * cs] = m.w;
}

extern "C" void kernel_launch(void* const* d_in, const int* in_sizes, int n_in,
                              void* d_out, int out_size)
{
    const float* data      = nullptr;
    const float* rois      = nullptr;
    const int*   batches   = nullptr;
    const float* scale_ptr = nullptr;

    for (int i = 0; i < n_in; ++i) {
        int sz = in_sizes[i];
        if (sz == 1)            scale_ptr = (const float*)d_in[i];
        else if (sz == 128)     batches   = (const int*)d_in[i];
        else if (sz == 512)     rois      = (const float*)d_in[i];
        else                    data      = (const float*)d_in[i];
    }

    float* out = (float*)d_out;

    dim3 tgrid(HW / 32, CC / 32, BB);     // 128 x 8 x 4 = 4096 blocks
    dim3 tblock(32, 8);
    transpose_kernel<<<tgrid, tblock>>>(data);

    pool_kernel<<<NROI * CROP_H * CROP_W, 64>>>(rois, batches, scale_ptr, out);
}